// round 8
// baseline (speedup 1.0000x reference)
#include <cuda_runtime.h>
#include <math.h>

// Problem constants
#define BATCH   128
#define TLEN    160000
#define NFFT    400
#define HOP     160
#define NFRAMES 1001
#define NFREQ   201
#define NMEL    80
#define PADLEN  200
#define TILE    8
#define RAW_LEN (HOP * (TILE - 1) + NFFT)   // 1520-sample span per 8-frame tile
#define NF0     11                          // Hermitian half of the radix-20 inner DFT
#define EPS_F   1.1920929e-07f

// Precomputed constants (filled once per launch by precompute_kernel)
__device__ float d_c400[400], d_s400[400];
__device__ float d_c20[20],  d_s20[20];
__device__ int   d_mel_lo[NMEL], d_mel_hi[NMEL];

__global__ void precompute_kernel(const float* __restrict__ melfb) {
    const int t = threadIdx.x;  // 512 threads, 1 block
    if (t < 400) {
        double s, c;
        sincospi(2.0 * (double)t / 400.0, &s, &c);
        d_c400[t] = (float)c;  d_s400[t] = (float)s;
    }
    if (t < 20) {
        double s, c;
        sincospi(2.0 * (double)t / 20.0, &s, &c);
        d_c20[t] = (float)c;  d_s20[t] = (float)s;
    }
    if (t >= 400 && t < 400 + NMEL) {
        const int m = t - 400;
        int lo = NFREQ, hi = 0;
        for (int f = 0; f < NFREQ; f++) {
            if (melfb[m * NFREQ + f] != 0.0f) { if (f < lo) lo = f; hi = f + 1; }
        }
        d_mel_lo[m] = lo;
        d_mel_hi[m] = hi;
    }
}

__global__ __launch_bounds__(256) void logmel_kernel(
    const float* __restrict__ audio,    // [128, 160000]
    const float* __restrict__ window,   // [400]
    const float* __restrict__ melfb,    // [80, 201]
    float* __restrict__ out)            // [128, 80, 1001]
{
    __shared__ float raw[RAW_LEN];
    __shared__ float win_s[NFFT];
    __shared__ float xw[TILE * NFFT];           // windowed frames [j][n]
    __shared__ float Yr[TILE * 20 * NF0];       // inner DFT [j][n2][f0], f0<=10
    __shared__ float Yi[TILE * 20 * NF0];
    __shared__ float P[TILE][NFREQ + 3];        // power spectra
    __shared__ float c400[400], s400[400];
    __shared__ float c20[20], s20[20];
    __shared__ float melres[NMEL * TILE];       // staged log-mel outputs [m][j]

    const int tid  = threadIdx.x;
    const int t0   = blockIdx.x * TILE;
    const int b    = blockIdx.y;
    const long base = (long)b * TLEN;

    // ---- Phase A: copy twiddle tables (L2-resident), window, raw span ----
    for (int k = tid; k < 400; k += 256) { c400[k] = d_c400[k]; s400[k] = d_s400[k]; }
    if (tid < 20) { c20[tid] = d_c20[tid]; s20[tid] = d_s20[tid]; }
    for (int i = tid; i < NFFT; i += 256) win_s[i] = window[i];
    for (int i = tid; i < RAW_LEN; i += 256) {
        int g = t0 * HOP + i - PADLEN;
        if (g < 0) g = -g;                        // reflect left (no edge repeat)
        if (g >= TLEN) g = 2 * (TLEN - 1) - g;    // reflect right
        raw[i] = audio[base + g];
    }
    __syncthreads();

    // ---- Phase B: window all 8 frames ----
    for (int v = tid; v < TILE * NFFT; v += 256) {
        const int j = v / NFFT;
        const int i = v - j * NFFT;
        xw[v] = raw[j * HOP + i] * win_s[i];
    }
    __syncthreads();

    // ---- Phase C: inner radix-20 DFT, Hermitian half ----
    // Y[j][n2][f0] = sum_{n1<20} xw[j][20*n1+n2] * W20^{-f0*n1},  f0 in [0,10]
    for (int t = tid; t < TILE * 20 * NF0; t += 256) {
        const int j  = t / (20 * NF0);
        const int r  = t - j * (20 * NF0);
        const int n2 = r / NF0;
        const int f0 = r - n2 * NF0;
        const float* xj = xw + j * NFFT + n2;
        float ar = 0.f, ai = 0.f;
        int k = 0;
        #pragma unroll
        for (int n1 = 0; n1 < 20; n1++) {
            const float xv = xj[20 * n1];
            ar += xv * c20[k];
            ai -= xv * s20[k];
            k += f0; if (k >= 20) k -= 20;
        }
        Yr[t] = ar;
        Yi[t] = ai;
    }
    __syncthreads();

    // ---- Phase D: outer DFT, twiddles register-cached, reused over 4 frames ----
    // X[f] = sum_{n2<20} W400^{-f*n2} * Y[n2][f mod 20]
    for (int t = tid; t < 2 * NFREQ; t += 256) {
        const int f  = t % NFREQ;
        const int jh = t / NFREQ;          // 0 or 1 -> frames [0..3] or [4..7]
        const int f0 = f % 20;
        const int i0 = (f0 <= 10) ? f0 : 20 - f0;
        const float sgn = (f0 <= 10) ? 1.0f : -1.0f;

        float cw[20], sw[20];
        int k = 0;
        #pragma unroll
        for (int n2 = 0; n2 < 20; n2++) {
            cw[n2] = c400[k];  sw[n2] = s400[k];
            k += f; if (k >= 400) k -= 400;
        }
        for (int j = jh * 4; j < jh * 4 + 4; j++) {
            const float* yrp = Yr + j * (20 * NF0) + i0;
            const float* yip = Yi + j * (20 * NF0) + i0;
            float re = 0.f, im = 0.f;
            #pragma unroll
            for (int n2 = 0; n2 < 20; n2++) {
                const float yr = yrp[n2 * NF0];
                const float yi = sgn * yip[n2 * NF0];
                re += cw[n2] * yr + sw[n2] * yi;   // (c - i s)(yr + i yi)
                im += cw[n2] * yi - sw[n2] * yr;
            }
            P[j][f] = re * re + im * im;
        }
    }
    __syncthreads();

    // ---- Phase E: sparse mel projection + log, thread per (frame, mel) ----
    for (int t = tid; t < TILE * NMEL; t += 256) {
        const int m = t % NMEL;
        const int j = t / NMEL;
        const int lo = d_mel_lo[m];
        const int hi = d_mel_hi[m];
        float sum = 0.f;
        for (int f = lo; f < hi; f++)
            sum += melfb[m * NFREQ + f] * P[j][f];
        melres[m * TILE + j] = logf(sum + EPS_F);
    }
    __syncthreads();

    // ---- Phase F: coalesced output stores (8-float runs per mel row) ----
    for (int v = tid; v < NMEL * TILE; v += 256) {
        const int m = v >> 3;
        const int j = v & 7;
        const int tt = t0 + j;
        if (tt < NFRAMES)
            out[((long)b * NMEL + m) * NFRAMES + tt] = melres[v];
    }
}

extern "C" void kernel_launch(void* const* d_in, const int* in_sizes, int n_in,
                              void* d_out, int out_size) {
    const float* audio  = (const float*)d_in[0];   // [128,160000]
    const float* window = (const float*)d_in[1];   // [400]
    const float* melfb  = (const float*)d_in[2];   // [80,201]
    float* out = (float*)d_out;                    // [128,80,1001]

    precompute_kernel<<<1, 512>>>(melfb);
    dim3 grid((NFRAMES + TILE - 1) / TILE, BATCH); // (126, 128)
    logmel_kernel<<<grid, 256>>>(audio, window, melfb, out);
}

// round 16
// speedup vs baseline: 1.8424x; 1.8424x over previous
#include <cuda_runtime.h>
#include <math.h>

// Problem constants
#define BATCH   128
#define TLEN    160000
#define NFFT    400
#define HOP     160
#define NFRAMES 1001
#define NFREQ   201
#define NMEL    80
#define PADLEN  200
#define TILE    8
#define RAW_LEN (HOP * (TILE - 1) + NFFT)   // 1520-sample span per 8-frame tile
#define NF0     11                          // Hermitian half of the radix-20 inner DFT
#define EPS_F   1.1920929e-07f

// Precomputed constants (filled once per launch by precompute_kernel)
__device__ float d_c400[400], d_s400[400];
__device__ float d_c20[20],  d_s20[20];
__device__ int   d_mel_lo[NMEL], d_mel_hi[NMEL];

__global__ void precompute_kernel(const float* __restrict__ melfb) {
    const int t = threadIdx.x;  // 512 threads, 1 block
    if (t < 400) {
        double s, c;
        sincospi(2.0 * (double)t / 400.0, &s, &c);
        d_c400[t] = (float)c;  d_s400[t] = (float)s;
    }
    if (t < 20) {
        double s, c;
        sincospi(2.0 * (double)t / 20.0, &s, &c);
        d_c20[t] = (float)c;  d_s20[t] = (float)s;
    }
    if (t >= 400 && t < 400 + NMEL) {
        const int m = t - 400;
        int lo = NFREQ, hi = 0;
        for (int f = 0; f < NFREQ; f++) {
            if (melfb[m * NFREQ + f] != 0.0f) { if (f < lo) lo = f; hi = f + 1; }
        }
        d_mel_lo[m] = lo;
        d_mel_hi[m] = hi;
    }
}

__global__ __launch_bounds__(256) void logmel_kernel(
    const float* __restrict__ audio,    // [128, 160000]
    const float* __restrict__ window,   // [400]
    const float* __restrict__ melfb,    // [80, 201]
    float* __restrict__ out)            // [128, 80, 1001]
{
    __shared__ float  raw[RAW_LEN];
    __shared__ float  win_s[NFFT];
    __shared__ float2 Ycx[TILE * 20 * NF0];     // inner DFT [j][n2][f0], f0<=10
    __shared__ float  P[TILE][NFREQ + 3];       // power spectra
    __shared__ float  melres[NMEL * TILE];      // staged log-mel outputs [m][j]

    const int tid  = threadIdx.x;
    const int t0   = blockIdx.x * TILE;
    const int b    = blockIdx.y;
    const long base = (long)b * TLEN;

    // ---- Phase A: window + raw span (reflect padding) ----
    for (int i = tid; i < NFFT; i += 256) win_s[i] = window[i];
    for (int i = tid; i < RAW_LEN; i += 256) {
        int g = t0 * HOP + i - PADLEN;
        if (g < 0) g = -g;                        // reflect left (no edge repeat)
        if (g >= TLEN) g = 2 * (TLEN - 1) - g;    // reflect right
        raw[i] = audio[base + g];
    }
    __syncthreads();

    // ---- Phase C: fused window + inner radix-20 DFT (Hermitian half) ----
    // Thread (j, n2) streams 20 samples once, produces all 11 f0 outputs.
    // Y[j][n2][f0] = sum_{n1<20} x[20*n1+n2]*win[20*n1+n2] * W20^{-f0*n1}
    if (tid < TILE * 20) {
        const int j  = tid / 20;
        const int n2 = tid - j * 20;

        // half-size radix-20 twiddle table in registers (compile-time indexed)
        float tc[NF0], ts[NF0];
        #pragma unroll
        for (int k = 0; k < NF0; k++) { tc[k] = d_c20[k]; ts[k] = d_s20[k]; }

        float ar[NF0], ai[NF0];
        #pragma unroll
        for (int f0 = 0; f0 < NF0; f0++) { ar[f0] = 0.f; ai[f0] = 0.f; }

        const float* rp = raw   + j * HOP + n2;
        const float* wp = win_s + n2;
        #pragma unroll
        for (int n1 = 0; n1 < 20; n1++) {
            const float xv = rp[20 * n1] * wp[20 * n1];
            #pragma unroll
            for (int f0 = 0; f0 < NF0; f0++) {
                const int kk = (f0 * n1) % 20;     // compile-time constant
                if (kk <= 10) {
                    ar[f0] += xv * tc[kk];
                    ai[f0] -= xv * ts[kk];
                } else {                            // c20[kk]=tc[20-kk], s20[kk]=-ts[20-kk]
                    ar[f0] += xv * tc[20 - kk];
                    ai[f0] += xv * ts[20 - kk];
                }
            }
        }
        float2* yo = Ycx + tid * NF0;
        #pragma unroll
        for (int f0 = 0; f0 < NF0; f0++) yo[f0] = make_float2(ar[f0], ai[f0]);
    }
    __syncthreads();

    // ---- Phase D: outer DFT via complex twiddle recurrence, 4 frames/thread ----
    // X[f] = sum_{n2<20} W400^{-f*n2} * Y[n2][f mod 20]
    for (int t = tid; t < 2 * NFREQ; t += 256) {
        int f = t, jh = 0;
        if (t >= NFREQ) { f = t - NFREQ; jh = 1; }
        const int   f0 = f % 20;
        const int   i0 = (f0 <= 10) ? f0 : 20 - f0;
        const float sg = (f0 <= 10) ? 1.0f : -1.0f;

        const float cs = d_c400[f];                // step = (cos, sin)(2*pi*f/400)
        const float sn = d_s400[f];
        float tr = 1.0f, ti = 0.0f;                // current twiddle (cos, sin)

        float re[4] = {0.f, 0.f, 0.f, 0.f};
        float im[4] = {0.f, 0.f, 0.f, 0.f};
        const float2* yb = Ycx + (jh * 4 * 20) * NF0 + i0;

        #pragma unroll
        for (int n2 = 0; n2 < 20; n2++) {
            const float tis = ti * sg;
            const float trs = tr * sg;
            #pragma unroll
            for (int q = 0; q < 4; q++) {
                const float2 y = yb[(q * 20 + n2) * NF0];
                re[q] += tr  * y.x + tis * y.y;    // (c - i s)(yr + i sg*yi)
                im[q] += trs * y.y - ti  * y.x;
            }
            const float ntr = tr * cs - ti * sn;   // advance twiddle: angle += 2*pi*f/400
            ti = tr * sn + ti * cs;
            tr = ntr;
        }
        #pragma unroll
        for (int q = 0; q < 4; q++)
            P[jh * 4 + q][f] = re[q] * re[q] + im[q] * im[q];
    }
    __syncthreads();

    // ---- Phase E: sparse mel projection + log, thread per (frame, mel) ----
    for (int t = tid; t < TILE * NMEL; t += 256) {
        const int m = t % NMEL;
        const int j = t / NMEL;
        const int lo = d_mel_lo[m];
        const int hi = d_mel_hi[m];
        float sum = 0.f;
        for (int f = lo; f < hi; f++)
            sum += melfb[m * NFREQ + f] * P[j][f];
        melres[m * TILE + j] = logf(sum + EPS_F);
    }
    __syncthreads();

    // ---- Phase F: coalesced output stores (8-float runs per mel row) ----
    for (int v = tid; v < NMEL * TILE; v += 256) {
        const int m = v >> 3;
        const int j = v & 7;
        const int tt = t0 + j;
        if (tt < NFRAMES)
            out[((long)b * NMEL + m) * NFRAMES + tt] = melres[v];
    }
}

extern "C" void kernel_launch(void* const* d_in, const int* in_sizes, int n_in,
                              void* d_out, int out_size) {
    const float* audio  = (const float*)d_in[0];   // [128,160000]
    const float* window = (const float*)d_in[1];   // [400]
    const float* melfb  = (const float*)d_in[2];   // [80,201]
    float* out = (float*)d_out;                    // [128,80,1001]

    precompute_kernel<<<1, 512>>>(melfb);
    dim3 grid((NFRAMES + TILE - 1) / TILE, BATCH); // (126, 128)
    logmel_kernel<<<grid, 256>>>(audio, window, melfb, out);
}